// round 6
// baseline (speedup 1.0000x reference)
#include <cuda_runtime.h>

// DisplacementVectorsASU — gather + per-edge affine transform.
//
// Inputs (metadata order):
//   d_in[0] frac_coords       float32  (100000, 3)
//   d_in[1] edge_indices      int32    (2, 4000000)
//   d_in[2] symmops           float32  (4000000, 4, 4)
//   d_in[3] cell_translations float32  (4000000, 3)
// Output: float32 (4000000, 3)
//
// R6 design (evidence so far):
//  - float4-packed node table: 1 LDG.128 per gather          (R3: -4us)
//  - default cache policy (evict-first hints cost +24us)      (R4)
//  - 2 edges/thread for gather MLP                            (R5: -2us)
//  - NEW: only gathers front-batched; symmops consumed per-edge to cut
//    peak regs 48->~40, restoring occupancy 60%->75% via
//    __launch_bounds__(256, 6). Gathers (L2 ~250cyc, divergent) are the
//    latency that needs per-thread MLP; symmop streams hide cross-warp.

#define NODE_CAP 131072
__device__ float4 g_frac4[NODE_CAP];

// One thread per node: 3 coalesced-ish scalar loads, one STG.128.
__global__ __launch_bounds__(512)
void pack_frac_kernel(const float* __restrict__ frac, int n)
{
    int i = blockIdx.x * blockDim.x + threadIdx.x;
    if (i < n) {
        float4 v;
        v.x = __ldg(frac + 3 * i + 0);
        v.y = __ldg(frac + 3 * i + 1);
        v.z = __ldg(frac + 3 * i + 2);
        v.w = 0.0f;
        g_frac4[i] = v;
    }
}

#define TPB   256
#define EPB   512   // edges per block (2 per thread)

__global__ __launch_bounds__(TPB, 6)
void displacement_kernel(const int*    __restrict__ ei,
                         const float4* __restrict__ sym,   // 4 float4 per edge
                         const float4* __restrict__ ct4,
                         float4*       __restrict__ out4,
                         int M)
{
    __shared__ float s_ct[EPB * 3];
    __shared__ float s_out[EPB * 3];

    const int tid       = threadIdx.x;
    const int blockBase = blockIdx.x * EPB;

    // ---- cooperative float4 load of cell_translations (coalesced) ----
    {
        const long f4base = (long)blockBase * 3 / 4;      // EPB*3 % 4 == 0
        #pragma unroll
        for (int i = tid; i < EPB * 3 / 4; i += TPB) {
            long idx = f4base + i;
            if (idx * 4 < (long)M * 3)
                ((float4*)s_ct)[i] = __ldg(ct4 + idx);
        }
    }
    __syncthreads();

    const int e0 = blockBase + tid;
    const int e1 = e0 + TPB;
    const bool v0 = (e0 < M);
    const bool v1 = (e1 < M);

    // ---- front-batch ONLY the long-latency divergent gathers ----
    int i0a = 0, i0b = 0, i1a = 0, i1b = 0;
    if (v0) { i0a = __ldg(ei + e0); i0b = __ldg(ei + M + e0); }
    if (v1) { i1a = __ldg(ei + e1); i1b = __ldg(ei + M + e1); }

    float4 fin0 = {0,0,0,0}, fo0 = {0,0,0,0};
    float4 fin1 = {0,0,0,0}, fo1 = {0,0,0,0};
    if (v0) { fin0 = __ldg(g_frac4 + i0a); fo0 = __ldg(g_frac4 + i0b); }
    if (v1) { fin1 = __ldg(g_frac4 + i1a); fo1 = __ldg(g_frac4 + i1b); }

    // ---- edge 0: load symmops, compute, retire registers ----
    if (v0) {
        const long sb = 4L * e0;
        const float4 a0 = __ldg(sym + sb + 0);
        const float4 a1 = __ldg(sym + sb + 1);
        const float4 a2 = __ldg(sym + sb + 2);
        float t0 = fmaf(a0.x, fo0.x, fmaf(a0.y, fo0.y, fmaf(a0.z, fo0.z, a0.w)));
        float t1 = fmaf(a1.x, fo0.x, fmaf(a1.y, fo0.y, fmaf(a1.z, fo0.z, a1.w)));
        float t2 = fmaf(a2.x, fo0.x, fmaf(a2.y, fo0.y, fmaf(a2.z, fo0.z, a2.w)));
        s_out[3 * tid + 0] = fin0.x - (t0 - floorf(t0) + s_ct[3 * tid + 0]);
        s_out[3 * tid + 1] = fin0.y - (t1 - floorf(t1) + s_ct[3 * tid + 1]);
        s_out[3 * tid + 2] = fin0.z - (t2 - floorf(t2) + s_ct[3 * tid + 2]);
    }

    // ---- edge 1 ----
    if (v1) {
        const int u = tid + TPB;
        const long sb = 4L * e1;
        const float4 b0 = __ldg(sym + sb + 0);
        const float4 b1 = __ldg(sym + sb + 1);
        const float4 b2 = __ldg(sym + sb + 2);
        float t0 = fmaf(b0.x, fo1.x, fmaf(b0.y, fo1.y, fmaf(b0.z, fo1.z, b0.w)));
        float t1 = fmaf(b1.x, fo1.x, fmaf(b1.y, fo1.y, fmaf(b1.z, fo1.z, b1.w)));
        float t2 = fmaf(b2.x, fo1.x, fmaf(b2.y, fo1.y, fmaf(b2.z, fo1.z, b2.w)));
        s_out[3 * u + 0] = fin1.x - (t0 - floorf(t0) + s_ct[3 * u + 0]);
        s_out[3 * u + 1] = fin1.y - (t1 - floorf(t1) + s_ct[3 * u + 1]);
        s_out[3 * u + 2] = fin1.z - (t2 - floorf(t2) + s_ct[3 * u + 2]);
    }
    __syncthreads();

    // ---- cooperative float4 store of the output (coalesced) ----
    {
        const long f4base = (long)blockBase * 3 / 4;
        #pragma unroll
        for (int i = tid; i < EPB * 3 / 4; i += TPB) {
            long idx = f4base + i;
            if (idx * 4 < (long)M * 3)
                out4[idx] = ((const float4*)s_out)[i];
        }
    }
}

extern "C" void kernel_launch(void* const* d_in, const int* in_sizes, int n_in,
                              void* d_out, int out_size)
{
    const float*  frac = (const float*) d_in[0];
    const int*    ei   = (const int*)   d_in[1];
    const float4* sym  = (const float4*)d_in[2];
    const float4* ct4  = (const float4*)d_in[3];
    float4*       out4 = (float4*)      d_out;

    const int n = in_sizes[0] / 3;      // node count
    const int M = in_sizes[1] / 2;      // edge count

    pack_frac_kernel<<<(n + 511) / 512, 512>>>(frac, n);

    const int blocks = (M + EPB - 1) / EPB;
    displacement_kernel<<<blocks, TPB>>>(ei, sym, ct4, out4, M);
}